// round 10
// baseline (speedup 1.0000x reference)
#include <cuda_runtime.h>
#include <cstdint>

#define B_SZ  8
#define SEQ   4096
#define HID   1024
#define NGRP  (SEQ / 32)     // 128 t-groups of 32 steps
#define DMAX  24             // FIR truncation: g[d] ~ 0.64*0.16^d -> 6e-20 at d=24
#define CHUNKS 16            // time-chunks for the SNN scan
#define CGRP   (NGRP / CHUNKS)  // 8 stored groups per chunk
#define WGRP   8             // warmup groups (256 steps): 0.9^256 ~ 2e-12
#define YC     256           // t-chunk per fused u+y block

// ---------------- scratch (device globals; no allocation allowed) ----------------
// bit (t&31) of word [b][t>>5][h] = spike(b,t,h). 4 MB.
__device__ unsigned g_bits[B_SZ][NGRP][HID];
__device__ float    g_g[DMAX];          // impulse response C A^d B
__device__ float    g_y[B_SZ][SEQ];     // y[b][t]

// ---------------- LIF step: float-mask form (masks exactly 0.0/1.0) --------------
// w09 = rn(0.9 * v_pre-reset), ns = 1-spike_prev, act = (r<=0), r exact int.
// Every FFMA multiplies by exact 0/1 so rounding == reference's mul+add.
struct SnnState { float w09, ns, act, r; };

__device__ __forceinline__ void snn_step(SnnState& st, float xk,
                                         float& macc, float mc)
{
    float v1 = __fmaf_rn(st.w09, st.ns, xk);          // rn(0.9*v_post + x)
    float ge; asm("set.ge.f32.f32 %0, %1, %2;" : "=f"(ge) : "f"(v1), "f"(1.0f));
    float s  = __fmul_rn(ge, st.act);                 // spike as 0.0/1.0
    st.w09   = __fmul_rn(v1, 0.9f);
    st.ns    = __fmaf_rn(-ge, st.act, 1.0f);          // 1 - spike (exact)
    float rd = fmaxf(__fadd_rn(st.r, -1.0f), 0.0f);   // max(r-1,0), exact
    st.r     = __fmaf_rn(s, 5.0f, rd);                // spike => rd==0 => 5
    asm("set.le.f32.f32 %0, %1, %2;" : "=f"(st.act) : "f"(st.r), "f"(0.0f));
    macc     = __fmaf_rn(s, mc, macc);                // exact bit accumulation
}

// ---------------- pass 1: LIF neurons -> spike bitmasks (+hidden g block) --------
// 128 snn blocks of 512 threads: block = (b, chunk); each thread runs TWO
// adjacent (b,h) lanes (float2 = 2 chains of in-warp ILP); a block covers the
// full 1024-h row, so each step reads one contiguous 4 KB row of x.
// Chunk c's 8 warm groups == chunk c-1's stored groups -> L2 reuse.
// Last block computes g[d] = C A^d B concurrently.
__global__ void __launch_bounds__(512) snn_kernel(const float* __restrict__ x,
                                                  const float* __restrict__ Ap,
                                                  const float* __restrict__ Bp,
                                                  const float* __restrict__ Cp)
{
    __shared__ float As[64 * 65];
    __shared__ float ws[64];
    __shared__ float red[2];

    if (blockIdx.x >= B_SZ * CHUNKS) {
        // ---- g block: g[d] = C . (A^d B), d = 0..DMAX-1 (tid<64 active) ----
        const int tid = threadIdx.x;
        for (int i = tid; i < 64 * 64; i += 512)
            As[(i >> 6) * 65 + (i & 63)] = Ap[i];
        float cv = 0.f, w = 0.f;
        if (tid < 64) { cv = Cp[tid]; w = Bp[tid]; ws[tid] = w; }
        __syncthreads();
        for (int d = 0; d < DMAX; d++) {
            if (tid < 64) {
                float p = cv * w;
                #pragma unroll
                for (int o = 16; o; o >>= 1) p += __shfl_down_sync(0xffffffffu, p, o);
                if ((tid & 31) == 0) red[tid >> 5] = p;
            }
            __syncthreads();
            if (tid == 0) g_g[d] = red[0] + red[1];
            if (d < DMAX - 1) {
                float wn = 0.f;
                if (tid < 64) {
                    float a0 = 0.f, a1 = 0.f, a2 = 0.f, a3 = 0.f;
                    #pragma unroll
                    for (int s = 0; s < 64; s += 4) {
                        a0 += As[tid * 65 + s + 0] * ws[s + 0];
                        a1 += As[tid * 65 + s + 1] * ws[s + 1];
                        a2 += As[tid * 65 + s + 2] * ws[s + 2];
                        a3 += As[tid * 65 + s + 3] * ws[s + 3];
                    }
                    wn = (a0 + a1) + (a2 + a3);
                }
                __syncthreads();
                if (tid < 64) ws[tid] = wn;
                __syncthreads();
                w = wn;
            }
        }
        return;
    }

    // ---- SNN path: 2 lanes per thread, full h-row per block ----
    const int blk  = blockIdx.x;               // 0..127
    const int c    = blk & (CHUNKS - 1);
    const int b    = blk >> 4;
    const int tid  = threadIdx.x;              // 0..511
    const int h    = tid * 2;

    const int warm    = (c == 0) ? 0 : WGRP;
    const int g0      = c * CGRP;
    const int tbegin  = g0 * 32 - warm * 32;
    const int ngroups = warm + CGRP;           // 8 or 16

    const float2* xp = (const float2*)(x + ((size_t)b * SEQ + tbegin) * HID + h);
    uint2* sbw = (uint2*)&g_bits[b][g0][h];
    const int HID2 = HID / 2;

    // 32-deep float2 buffer, constant indices only (no local-mem demotion);
    // value loaded at (gg,i) is consumed at (gg+1,i): 32-step prefetch distance.
    float2 buf[32];
    #pragma unroll
    for (int i = 0; i < 32; i++) buf[i] = xp[(size_t)i * HID2];
    const float2* xld = xp + (size_t)32 * HID2;

    SnnState s0 = {0,1,1,0}, s1 = {0,1,1,0};

    for (int gg = 0; gg < ngroups; gg++) {
        const bool pf = (gg + 1 < ngroups);
        float m0l = 0, m0h = 0, m1l = 0, m1h = 0;

        #pragma unroll
        for (int i = 0; i < 32; i++) {
            float2 xk = buf[i];
            if (pf) buf[i] = xld[(size_t)i * HID2];    // prefetch next group
            const float mc = (float)(1u << (i & 15));
            if (i < 16) {
                snn_step(s0, xk.x, m0l, mc);
                snn_step(s1, xk.y, m1l, mc);
            } else {
                snn_step(s0, xk.x, m0h, mc);
                snn_step(s1, xk.y, m1h, mc);
            }
        }
        xld += (size_t)32 * HID2;
        if (gg >= warm) {
            uint2 mv;
            mv.x = __float2uint_rn(m0l) | (__float2uint_rn(m0h) << 16);
            mv.y = __float2uint_rn(m1l) | (__float2uint_rn(m1h) << 16);
            *sbw = mv;                          // coalesced 8B store
            sbw += HID2;
        }
    }
}

// ---------------- pass 2: fused u (popcount transpose) + y (24-tap FIR) ----------
// grid: B_SZ*16 blocks, 256 threads; block (b,yc) produces y[b][yc*256 .. +256).
__global__ void __launch_bounds__(256) uy_kernel(const float* __restrict__ Dp)
{
    __shared__ unsigned wsm[HID];
    __shared__ int   part[8 * 32];
    __shared__ float u_s[32 + YC];   // u_s[i] = u[t0 - 32 + i]
    __shared__ float g_s[DMAX];

    const int b   = blockIdx.x >> 4;
    const int yc  = blockIdx.x & 15;
    const int t0  = yc * YC;
    const int gb  = yc * (YC / 32);
    const int tid = threadIdx.x;
    const int wid = tid >> 5, lane = tid & 31;

    if (tid < DMAX) g_s[tid] = g_g[tid];

    for (int j = -1; j < YC / 32; j++) {        // 1 halo group + 8 own groups
        const int g  = gb + j;
        const int i0 = 32 + j * 32;
        if (g < 0) {
            if (tid < 32) u_s[i0 + tid] = 0.0f;
            continue;
        }
        ((uint4*)wsm)[tid] = ((const uint4*)&g_bits[b][g][0])[tid];
        __syncthreads();
        int cnt = 0;
        #pragma unroll 8
        for (int i2 = 0; i2 < 128; i2++)
            cnt += (int)((wsm[wid * 128 + i2] >> lane) & 1u);
        part[wid * 32 + lane] = cnt;
        __syncthreads();
        if (tid < 32) {
            int tot = 0;
            #pragma unroll
            for (int ww = 0; ww < 8; ww++) tot += part[ww * 32 + tid];
            u_s[i0 + tid] = (float)tot * (1.0f / (float)HID);
        }
        __syncthreads();
    }

    const float Ds = *Dp;
    {
        const int i = tid;                      // YC == blockDim.x
        float acc = Ds * u_s[32 + i];
        #pragma unroll
        for (int d = 0; d < DMAX; d++)
            acc += g_s[d] * u_s[32 + i - d];
        g_y[b][t0 + i] = acc;
    }
}

// ---------------- pass 3: out[b][t][h] = spike_bit + y[b][t] ---------------------
// grid: B_SZ * NGRP * 2 blocks; block covers 16 t x 1024 h (64 KB of output).
__global__ void __launch_bounds__(256) out_kernel(float4* __restrict__ out)
{
    __shared__ float ys[16], ys1[16];

    const int blk  = blockIdx.x;
    const int half = blk & 1;
    const int g    = (blk >> 1) & (NGRP - 1);
    const int b    = blk >> 8;
    const int tid  = threadIdx.x;            // h4 = tid: hidden 4*tid..4*tid+3

    if (tid < 16) {
        float yv = g_y[b][g * 32 + half * 16 + tid];
        ys[tid]  = yv;
        ys1[tid] = yv + 1.0f;
    }
    const uint4 wv = ((const uint4*)&g_bits[b][g][0])[tid];
    __syncthreads();

    float4* base = out + ((size_t)(b * SEQ + g * 32 + half * 16) * HID) / 4 + tid;
    #pragma unroll
    for (int t = 0; t < 16; t++) {
        const unsigned bit = 1u << (half * 16 + t);
        const float y  = ys[t];
        const float y1 = ys1[t];
        float4 o;
        o.x = (wv.x & bit) ? y1 : y;
        o.y = (wv.y & bit) ? y1 : y;
        o.z = (wv.z & bit) ? y1 : y;
        o.w = (wv.w & bit) ? y1 : y;
        __stcs(&base[(size_t)t * (HID / 4)], o);
    }
}

// ---------------- launch ----------------------------------------------------------
extern "C" void kernel_launch(void* const* d_in, const int* in_sizes, int n_in,
                              void* d_out, int out_size)
{
    const float* x  = (const float*)d_in[0];   // (8, 4096, 1024) f32
    const float* A  = (const float*)d_in[1];   // (64, 64)
    const float* Bv = (const float*)d_in[2];   // (64, 1)
    const float* Cv = (const float*)d_in[3];   // (1, 64)
    const float* Dp = (const float*)d_in[4];   // (1, 1)

    snn_kernel<<<B_SZ * CHUNKS + 1, 512>>>(x, A, Bv, Cv);
    uy_kernel<<<B_SZ * 16, 256>>>(Dp);
    out_kernel<<<B_SZ * NGRP * 2, 256>>>((float4*)d_out);
}

// round 11
// speedup vs baseline: 1.0624x; 1.0624x over previous
#include <cuda_runtime.h>
#include <cstdint>

#define B_SZ  8
#define SEQ   4096
#define HID   1024
#define HID2  (HID / 2)
#define HID4  (HID / 4)
#define DMAX  24             // FIR truncation: g[d] ~ 0.64*0.16^d -> 6e-20 at d=24
#define CHUNKS 16            // time-chunks; block = (b, chunk) covers full h-row
#define CGRP   8             // stored 32-step groups per chunk
#define WGRP   6             // warmup groups (192 steps): 0.9^192 ~ 1.7e-9

// ---------------- scratch (device globals; no allocation allowed) ----------------
__device__ float g_g[DMAX];             // impulse response C A^d B

// ---------------- kernel 0: impulse response g[d] = C * A^d * B ------------------
__global__ void g_kernel(const float* __restrict__ A,
                         const float* __restrict__ Bv,
                         const float* __restrict__ Cv)
{
    __shared__ float As[64 * 65];
    __shared__ float ws[64];
    __shared__ float red[2];

    const int tid = threadIdx.x;        // 64 threads, state index n = tid
    for (int i = tid; i < 64 * 64; i += 64)
        As[(i >> 6) * 65 + (i & 63)] = A[i];
    const float cv = Cv[tid];
    float w = Bv[tid];
    ws[tid] = w;
    __syncthreads();
    for (int d = 0; d < DMAX; d++) {
        float p = cv * w;
        #pragma unroll
        for (int o = 16; o; o >>= 1) p += __shfl_down_sync(0xffffffffu, p, o);
        if ((tid & 31) == 0) red[tid >> 5] = p;
        __syncthreads();
        if (tid == 0) g_g[d] = red[0] + red[1];
        if (d < DMAX - 1) {
            float a0 = 0.f, a1 = 0.f, a2 = 0.f, a3 = 0.f;
            #pragma unroll
            for (int s = 0; s < 64; s += 4) {
                a0 += As[tid * 65 + s + 0] * ws[s + 0];
                a1 += As[tid * 65 + s + 1] * ws[s + 1];
                a2 += As[tid * 65 + s + 2] * ws[s + 2];
                a3 += As[tid * 65 + s + 3] * ws[s + 3];
            }
            float wn = (a0 + a1) + (a2 + a3);
            __syncthreads();
            ws[tid] = wn;
            __syncthreads();
            w = wn;
        }
    }
}

// ---------------- LIF step: float-mask form (masks exactly 0.0/1.0) --------------
// w09 = rn(0.9 * v_pre-reset), ns = 1-spike_prev, act = (r<=0), r exact int.
// Every FFMA multiplies by exact 0/1 so rounding == reference's mul+add.
struct SnnState { float w09, ns, act, r; };

__device__ __forceinline__ void snn_step(SnnState& st, float xk,
                                         float& macc, float mc)
{
    float v1 = __fmaf_rn(st.w09, st.ns, xk);          // rn(0.9*v_post + x)
    float ge; asm("set.ge.f32.f32 %0, %1, %2;" : "=f"(ge) : "f"(v1), "f"(1.0f));
    float s  = __fmul_rn(ge, st.act);                 // spike as 0.0/1.0
    st.w09   = __fmul_rn(v1, 0.9f);
    st.ns    = __fmaf_rn(-ge, st.act, 1.0f);          // 1 - spike (exact)
    float rd = fmaxf(__fadd_rn(st.r, -1.0f), 0.0f);   // max(r-1,0), exact
    st.r     = __fmaf_rn(s, 5.0f, rd);                // spike => rd==0 => 5
    asm("set.le.f32.f32 %0, %1, %2;" : "=f"(st.act) : "f"(st.r), "f"(0.0f));
    macc     = __fmaf_rn(s, mc, macc);                // exact bit accumulation
}

// ---------------- fused kernel: scan + u + y(FIR) + output write -----------------
// 128 blocks of 512 threads: block = (b, chunk) owns the FULL 1024-h row for its
// 256-step stored range (+192-step warmup). Per 32-step group it pipelines:
//   scan (regs) -> masks to smem -> popcount-transpose u -> 24-tap FIR y ->
//   write out[b,t,:] = spike + y[t]   (no global scratch round-trip at all).
// Halo u for the FIR comes from the last warm group (state converged ~1e-9).
__global__ void __launch_bounds__(512) fused_kernel(const float* __restrict__ x,
                                                    const float* __restrict__ Dp,
                                                    float* __restrict__ out)
{
    __shared__ unsigned wsm[HID];        // masks of current group: word[h], bit=t
    __shared__ int   part[16 * 32];      // per-warp partial popcounts
    __shared__ float u_s[64];            // [0..31]=prev group u, [32..63]=cur
    __shared__ float y_s[32], y1_s[32];
    __shared__ float g_s[DMAX];

    const int blk  = blockIdx.x;         // 0..127
    const int c    = blk & (CHUNKS - 1);
    const int b    = blk >> 4;
    const int tid  = threadIdx.x;        // 0..511
    const int wid  = tid >> 5, lane = tid & 31;
    const int h    = tid * 2;            // 2 lanes per thread

    const int warm    = c ? WGRP : 0;
    const int g0      = c * CGRP;
    const int tbegin  = (g0 - warm) * 32;
    const int ngroups = warm + CGRP;     // 8 or 14

    if (tid < DMAX) g_s[tid] = g_g[tid];
    if (tid < 32)   u_s[tid] = 0.0f;     // halo for chunk 0
    const float Ds = __ldg(Dp);

    const float2* xp = (const float2*)(x + ((size_t)b * SEQ + tbegin) * HID) + tid;
    float4* out4 = (float4*)(out + ((size_t)b * SEQ + g0 * 32) * HID);

    // 32-deep float2 register buffer, constant indices only (no local-mem spill);
    // value loaded at (gg,i) is consumed at (gg+1,i): 32-step prefetch distance.
    float2 buf[32];
    #pragma unroll
    for (int i = 0; i < 32; i++) buf[i] = xp[(size_t)i * HID2];
    const float2* xld = xp + (size_t)32 * HID2;

    SnnState s0 = {0,1,1,0}, s1 = {0,1,1,0};

    for (int gg = 0; gg < ngroups; gg++) {
        const bool pf = (gg + 1 < ngroups);
        float m0l = 0, m0h = 0, m1l = 0, m1h = 0;

        #pragma unroll
        for (int i = 0; i < 32; i++) {
            float2 xk = buf[i];
            if (pf) buf[i] = xld[(size_t)i * HID2];    // prefetch next group
            const float mc = (float)(1u << (i & 15));
            if (i < 16) { snn_step(s0, xk.x, m0l, mc); snn_step(s1, xk.y, m1l, mc); }
            else        { snn_step(s0, xk.x, m0h, mc); snn_step(s1, xk.y, m1h, mc); }
        }
        xld += (size_t)32 * HID2;

        if (gg < warm - 1) continue;     // pure warmup group (uniform branch)

        uint2 mv;
        mv.x = __float2uint_rn(m0l) | (__float2uint_rn(m0h) << 16);
        mv.y = __float2uint_rn(m1l) | (__float2uint_rn(m1h) << 16);

        __syncthreads();                               // wsm / y / u-slide quiesced
        *(uint2*)&wsm[h] = mv;
        __syncthreads();

        // u[cur]: popcount transpose (16 warps x 64 words each)
        int cnt = 0;
        #pragma unroll 16
        for (int i2 = 0; i2 < 64; i2++)
            cnt += (int)((wsm[wid * 64 + i2] >> lane) & 1u);
        part[wid * 32 + lane] = cnt;
        __syncthreads();
        if (tid < 32) {
            int tot = 0;
            #pragma unroll
            for (int w2 = 0; w2 < 16; w2++) tot += part[w2 * 32 + tid];
            u_s[32 + tid] = (float)tot * (1.0f / (float)HID);
        }
        __syncthreads();
        if (tid < 32) {                                // y = D*u + g (*) u
            float acc = Ds * u_s[32 + tid];
            #pragma unroll
            for (int d = 0; d < DMAX; d++)
                acc += g_s[d] * u_s[32 + tid - d];
            y_s[tid]  = acc;
            y1_s[tid] = acc + 1.0f;
        }
        __syncthreads();

        if (gg >= warm) {
            // write 32 t x 1024 h: thread = (quad q, t-half hf); STG.128, 512B/warp
            const int q  = tid & 255;
            const int hf = tid >> 8;
            const uint4 w4 = ((const uint4*)wsm)[q];
            float4* rowb = out4 + (size_t)(gg - warm) * 32 * HID4 + q;
            #pragma unroll
            for (int k = 0; k < 16; k++) {
                const int t = hf * 16 + k;
                const float y = y_s[t], y1 = y1_s[t];
                float4 o;
                o.x = ((w4.x >> t) & 1u) ? y1 : y;
                o.y = ((w4.y >> t) & 1u) ? y1 : y;
                o.z = ((w4.z >> t) & 1u) ? y1 : y;
                o.w = ((w4.w >> t) & 1u) ? y1 : y;
                __stcs(&rowb[(size_t)t * HID4], o);
            }
        }
        if (tid < 32) u_s[tid] = u_s[32 + tid];        // slide cur -> prev
    }
}

// ---------------- launch ----------------------------------------------------------
extern "C" void kernel_launch(void* const* d_in, const int* in_sizes, int n_in,
                              void* d_out, int out_size)
{
    const float* x  = (const float*)d_in[0];   // (8, 4096, 1024) f32
    const float* A  = (const float*)d_in[1];   // (64, 64)
    const float* Bv = (const float*)d_in[2];   // (64, 1)
    const float* Cv = (const float*)d_in[3];   // (1, 64)
    const float* Dp = (const float*)d_in[4];   // (1, 1)

    g_kernel<<<1, 64>>>(A, Bv, Cv);
    fused_kernel<<<B_SZ * CHUNKS, 512>>>(x, Dp, (float*)d_out);
}

// round 12
// speedup vs baseline: 1.1444x; 1.0772x over previous
#include <cuda_runtime.h>
#include <cstdint>

#define B_SZ  8
#define SEQ   4096
#define HID   1024
#define HID2  (HID / 2)
#define HID4  (HID / 4)
#define DMAX  24             // FIR truncation: g[d] ~ 0.64*0.16^d -> 6e-20 at d=24
#define CHUNKS 16            // time-chunks; block = (b, chunk) covers full h-row
#define CGRP   8             // stored 32-step groups per chunk
#define WGRP   6             // warmup groups (192 steps): 0.9^192 ~ 1.7e-9

// ---------------- LIF step: float-mask form (masks exactly 0.0/1.0) --------------
// w09 = rn(0.9 * v_pre-reset), ns = 1-spike_prev, act = (r<=0), r exact int.
// Every FFMA multiplies by exact 0/1 so rounding == reference's mul+add.
struct SnnState { float w09, ns, act, r; };

__device__ __forceinline__ void snn_step(SnnState& st, float xk,
                                         float& macc, float mc)
{
    float v1 = __fmaf_rn(st.w09, st.ns, xk);          // rn(0.9*v_post + x)
    float ge; asm("set.ge.f32.f32 %0, %1, %2;" : "=f"(ge) : "f"(v1), "f"(1.0f));
    float s  = __fmul_rn(ge, st.act);                 // spike as 0.0/1.0
    st.w09   = __fmul_rn(v1, 0.9f);
    st.ns    = __fmaf_rn(-ge, st.act, 1.0f);          // 1 - spike (exact)
    float rd = fmaxf(__fadd_rn(st.r, -1.0f), 0.0f);   // max(r-1,0), exact
    st.r     = __fmaf_rn(s, 5.0f, rd);                // spike => rd==0 => 5
    asm("set.le.f32.f32 %0, %1, %2;" : "=f"(st.act) : "f"(st.r), "f"(0.0f));
    macc     = __fmaf_rn(s, mc, macc);                // exact bit accumulation
}

// ---------------- single fused kernel: g + scan + u + y(FIR) + write -------------
// 128 blocks of 512 threads: block = (b, chunk) owns the FULL 1024-h row for its
// 256-step stored range (+192-step warmup). Each block first computes the SSM
// impulse response g[d]=C A^d B inline (~5k cyc, 8 threads/row + shfl octet
// reduction; overlapped with the initial x prefetch), then per 32-step group:
//   scan (regs) -> masks to smem -> popcount-transpose u -> 24-tap FIR y ->
//   write out[b,t,:] = spike + y[t]   (no global scratch, no extra launches).
__global__ void __launch_bounds__(512) fused_kernel(const float* __restrict__ x,
                                                    const float* __restrict__ Ap,
                                                    const float* __restrict__ Bp,
                                                    const float* __restrict__ Cp,
                                                    const float* __restrict__ Dp,
                                                    float* __restrict__ out)
{
    __shared__ float As[64 * 65];        // A, padded rows
    __shared__ float Wall[DMAX][64];     // Krylov vectors A^d B
    __shared__ float wping[2][64];
    __shared__ float cs[64];
    __shared__ float g_s[DMAX];
    __shared__ unsigned wsm[HID];        // masks of current group: word[h], bit=t
    __shared__ int   part[16 * 32];      // per-warp partial popcounts
    __shared__ float u_s[64];            // [0..31]=prev group u, [32..63]=cur
    __shared__ float y_s[32], y1_s[32];

    const int blk  = blockIdx.x;         // 0..127
    const int c    = blk & (CHUNKS - 1);
    const int b    = blk >> 4;
    const int tid  = threadIdx.x;        // 0..511
    const int wid  = tid >> 5, lane = tid & 31;
    const int h    = tid * 2;            // 2 lanes per thread

    const int warm    = c ? WGRP : 0;
    const int g0      = c * CGRP;
    const int tbegin  = (g0 - warm) * 32;
    const int ngroups = warm + CGRP;     // 8 or 14

    const float2* xp = (const float2*)(x + ((size_t)b * SEQ + tbegin) * HID) + tid;
    float4* out4 = (float4*)(out + ((size_t)b * SEQ + g0 * 32) * HID);

    // issue the x prefetch FIRST so DRAM latency overlaps the g computation.
    float2 buf[32];
    #pragma unroll
    for (int i = 0; i < 32; i++) buf[i] = xp[(size_t)i * HID2];
    const float2* xld = xp + (size_t)32 * HID2;

    // ---- inline g: W_0 = B; W_d = A W_{d-1}; then g[d] = C . W_d -----------------
    for (int i = tid; i < 64 * 64; i += 512)
        As[(i >> 6) * 65 + (i & 63)] = Ap[i];
    if (tid < 64) {
        cs[tid] = Cp[tid];
        float b0 = Bp[tid];
        wping[0][tid] = b0;
        Wall[0][tid]  = b0;
    }
    __syncthreads();
    {
        const int row = tid >> 3, sub = tid & 7;   // 8 threads per row
        for (int d = 1; d < DMAX; d++) {
            const float* wprev = wping[(d - 1) & 1];
            float p = 0.f;
            #pragma unroll
            for (int j = 0; j < 8; j++)
                p += As[row * 65 + sub * 8 + j] * wprev[sub * 8 + j];
            p += __shfl_xor_sync(0xffffffffu, p, 1);
            p += __shfl_xor_sync(0xffffffffu, p, 2);
            p += __shfl_xor_sync(0xffffffffu, p, 4);
            if (sub == 0) { wping[d & 1][row] = p; Wall[d][row] = p; }
            __syncthreads();
        }
        if (tid < DMAX * 8) {                      // all 24 dots in parallel
            const int d = tid >> 3, s8 = (tid & 7) * 8;
            float p = 0.f;
            #pragma unroll
            for (int j = 0; j < 8; j++) p += cs[s8 + j] * Wall[d][s8 + j];
            p += __shfl_xor_sync(0xffffffffu, p, 1);
            p += __shfl_xor_sync(0xffffffffu, p, 2);
            p += __shfl_xor_sync(0xffffffffu, p, 4);
            if ((tid & 7) == 0) g_s[d] = p;
        }
        if (tid < 32) u_s[tid] = 0.0f;             // halo for chunk 0
        __syncthreads();
    }
    const float Ds = __ldg(Dp);

    // ---- scan + per-group epilogue ----------------------------------------------
    SnnState s0 = {0,1,1,0}, s1 = {0,1,1,0};

    for (int gg = 0; gg < ngroups; gg++) {
        const bool pf = (gg + 1 < ngroups);
        float m0l = 0, m0h = 0, m1l = 0, m1h = 0;

        #pragma unroll
        for (int i = 0; i < 32; i++) {
            float2 xk = buf[i];
            if (pf) buf[i] = xld[(size_t)i * HID2];    // prefetch next group
            const float mc = (float)(1u << (i & 15));
            if (i < 16) { snn_step(s0, xk.x, m0l, mc); snn_step(s1, xk.y, m1l, mc); }
            else        { snn_step(s0, xk.x, m0h, mc); snn_step(s1, xk.y, m1h, mc); }
        }
        xld += (size_t)32 * HID2;

        if (gg < warm - 1) continue;     // pure warmup group (uniform branch)

        uint2 mv;
        mv.x = __float2uint_rn(m0l) | (__float2uint_rn(m0h) << 16);
        mv.y = __float2uint_rn(m1l) | (__float2uint_rn(m1h) << 16);

        __syncthreads();                               // wsm / y / u-slide quiesced
        *(uint2*)&wsm[h] = mv;
        __syncthreads();

        // u[cur]: popcount transpose (16 warps x 64 words each)
        int cnt = 0;
        #pragma unroll 16
        for (int i2 = 0; i2 < 64; i2++)
            cnt += (int)((wsm[wid * 64 + i2] >> lane) & 1u);
        part[wid * 32 + lane] = cnt;
        __syncthreads();
        if (tid < 32) {
            int tot = 0;
            #pragma unroll
            for (int w2 = 0; w2 < 16; w2++) tot += part[w2 * 32 + tid];
            u_s[32 + tid] = (float)tot * (1.0f / (float)HID);
        }
        __syncthreads();
        if (tid < 32) {                                // y = D*u + g (*) u
            float acc = Ds * u_s[32 + tid];
            #pragma unroll
            for (int d = 0; d < DMAX; d++)
                acc += g_s[d] * u_s[32 + tid - d];
            y_s[tid]  = acc;
            y1_s[tid] = acc + 1.0f;
        }
        __syncthreads();

        if (gg >= warm) {
            // write 32 t x 1024 h: thread = (quad q, t-half hf); STG.128, 512B/warp
            const int q  = tid & 255;
            const int hf = tid >> 8;
            const uint4 w4 = ((const uint4*)wsm)[q];
            float4* rowb = out4 + (size_t)(gg - warm) * 32 * HID4 + q;
            #pragma unroll
            for (int k = 0; k < 16; k++) {
                const int t = hf * 16 + k;
                const float y = y_s[t], y1 = y1_s[t];
                float4 o;
                o.x = ((w4.x >> t) & 1u) ? y1 : y;
                o.y = ((w4.y >> t) & 1u) ? y1 : y;
                o.z = ((w4.z >> t) & 1u) ? y1 : y;
                o.w = ((w4.w >> t) & 1u) ? y1 : y;
                __stcs(&rowb[(size_t)t * HID4], o);
            }
        }
        if (tid < 32) u_s[tid] = u_s[32 + tid];        // slide cur -> prev
    }
}

// ---------------- launch ----------------------------------------------------------
extern "C" void kernel_launch(void* const* d_in, const int* in_sizes, int n_in,
                              void* d_out, int out_size)
{
    const float* x  = (const float*)d_in[0];   // (8, 4096, 1024) f32
    const float* A  = (const float*)d_in[1];   // (64, 64)
    const float* Bv = (const float*)d_in[2];   // (64, 1)
    const float* Cv = (const float*)d_in[3];   // (1, 64)
    const float* Dp = (const float*)d_in[4];   // (1, 1)

    fused_kernel<<<B_SZ * CHUNKS, 512>>>(x, A, Bv, Cv, Dp, (float*)d_out);
}